// round 10
// baseline (speedup 1.0000x reference)
#include <cuda_runtime.h>
#include <cuda_fp16.h>
#include <cstdint>
#include <math.h>

// ----------------------------------------------------------------------------
// Problem constants
// ----------------------------------------------------------------------------
#define BATCH 8192
#define FDIM  256
#define NBL   8
#define BF    (BATCH * FDIM)   // 2,097,152

// Fused GEMM tiling: CTA = 64 batch x 32 features, ALL 8 blades, L+R.
#define TM 64
#define TN 32
#define KT 32
#define SPADH 40               // smem row stride (halves): conflict-free LDS/LDSM

// smem layout (halves): stage s at s*STG_H
//   A planes: 8 x 64 x SPADH at 0
//   B mats  : 8 x 32 x SPADH at AOFF_H   (mat = grade*2 + side)
#define AOFF_H (8 * 64 * SPADH)            // 20480
#define STG_H  (AOFF_H + 8 * 32 * SPADH)   // 30720
#define STG_B  (STG_H * 2)                 // 61440 bytes
#define PAR_B  (2 * STG_B)                 // params byte offset
#define SMEM_TOTAL (PAR_B + 800 * 4)       // + 32 cols x (4+20+1) floats = 126080

// ----------------------------------------------------------------------------
// Scratch (device globals; no allocation allowed)
// ----------------------------------------------------------------------------
__device__ __half g_xt[(size_t)NBL * BF];   // planes [i][b][k], fp16
__device__ __half g_wl[4 * FDIM * FDIM];    // [g][n][k] fp16
__device__ __half g_wr[4 * FDIM * FDIM];    // [g][n][k] fp16

// ----------------------------------------------------------------------------
// helpers (base-ISA only: mma.sync + cp.async + ldmatrix)
// ----------------------------------------------------------------------------
__device__ __forceinline__ uint32_t smem_u32(const void* p) {
    uint32_t a;
    asm("{ .reg .u64 t; cvta.to.shared.u64 t, %1; cvt.u32.u64 %0, t; }"
        : "=r"(a) : "l"(p));
    return a;
}

__device__ __forceinline__ void cp16(uint32_t s, const void* g) {
    asm volatile("cp.async.cg.shared.global [%0], [%1], 16;" :: "r"(s), "l"(g));
}

#define CP_COMMIT() asm volatile("cp.async.commit_group;" ::: "memory")
#define CP_WAIT(n)  asm volatile("cp.async.wait_group %0;" :: "n"(n) : "memory")

#define LDSM4(r, addr) \
    asm volatile("ldmatrix.sync.aligned.m8n8.x4.shared.b16 {%0,%1,%2,%3}, [%4];" \
        : "=r"((r)[0]), "=r"((r)[1]), "=r"((r)[2]), "=r"((r)[3]) : "r"(addr))

#define MMA_FP16(d, a, b0r, b1r) \
    asm volatile( \
        "mma.sync.aligned.m16n8k16.row.col.f32.f16.f16.f32 " \
        "{%0,%1,%2,%3}, {%4,%5,%6,%7}, {%8,%9}, {%0,%1,%2,%3};" \
        : "+f"((d)[0]), "+f"((d)[1]), "+f"((d)[2]), "+f"((d)[3]) \
        : "r"((a)[0]), "r"((a)[1]), "r"((a)[2]), "r"((a)[3]), \
          "r"(b0r), "r"(b1r))

// ----------------------------------------------------------------------------
// Kernel 1: transpose x [B,F,8] -> fp16 planes [i][b][k]
// ----------------------------------------------------------------------------
__global__ void __launch_bounds__(256) k_transpose_x(
    const float* __restrict__ x, __half* __restrict__ xt)
{
    int t = blockIdx.x * 256 + threadIdx.x;   // t = b*FDIM + k
    size_t src = (size_t)t * NBL;
    float4 v0 = *(const float4*)&x[src];
    float4 v1 = *(const float4*)&x[src + 4];
    xt[0 * (size_t)BF + t] = __float2half_rn(v0.x);
    xt[1 * (size_t)BF + t] = __float2half_rn(v0.y);
    xt[2 * (size_t)BF + t] = __float2half_rn(v0.z);
    xt[3 * (size_t)BF + t] = __float2half_rn(v0.w);
    xt[4 * (size_t)BF + t] = __float2half_rn(v1.x);
    xt[5 * (size_t)BF + t] = __float2half_rn(v1.y);
    xt[6 * (size_t)BF + t] = __float2half_rn(v1.z);
    xt[7 * (size_t)BF + t] = __float2half_rn(v1.w);
}

// ----------------------------------------------------------------------------
// Kernel 2: de-interleave weights [n, k, 4] -> fp16 [g][n][k]
// ----------------------------------------------------------------------------
__global__ void __launch_bounds__(256) k_prep_w(
    const float* __restrict__ wl, const float* __restrict__ wr,
    __half* __restrict__ wlt, __half* __restrict__ wrt)
{
    int t = blockIdx.x * 256 + threadIdx.x;   // t = n*FDIM + k
    size_t src = (size_t)t * 4;
    float4 a = *(const float4*)&wl[src];
    float4 b = *(const float4*)&wr[src];
    wlt[0 * FDIM * FDIM + t] = __float2half_rn(a.x);
    wlt[1 * FDIM * FDIM + t] = __float2half_rn(a.y);
    wlt[2 * FDIM * FDIM + t] = __float2half_rn(a.z);
    wlt[3 * FDIM * FDIM + t] = __float2half_rn(a.w);
    wrt[0 * FDIM * FDIM + t] = __float2half_rn(b.x);
    wrt[1 * FDIM * FDIM + t] = __float2half_rn(b.y);
    wrt[2 * FDIM * FDIM + t] = __float2half_rn(b.z);
    wrt[3 * FDIM * FDIM + t] = __float2half_rn(b.w);
}

// ----------------------------------------------------------------------------
// Kernel 3: FUSED — 16 GEMMs (8 blades x {L,R}) + normalize + geometric
// product + bias + scale, all in one kernel. grid (128, 8), 256 threads.
// ----------------------------------------------------------------------------
__global__ void __launch_bounds__(256, 1) k_fused(
    const __half* __restrict__ xt,
    const __half* __restrict__ wlt, const __half* __restrict__ wrt,
    const float* __restrict__ x,
    const float* __restrict__ b_left, const float* __restrict__ a_norm,
    const float* __restrict__ w_gp, float* __restrict__ out)
{
    extern __shared__ char dynsmem[];
    __half* tiles = (__half*)dynsmem;
    float*  pAn = (float*)(dynsmem + PAR_B);          // [32][4]
    float*  pWg = pAn + 128;                           // [32][20]
    float*  pBl = pWg + 640;                           // [32]

    const int tid  = threadIdx.x;
    const int lane = tid & 31;
    const int w    = tid >> 5;
    const int gq   = lane >> 2;
    const int tq   = lane & 3;

    const int b0  = blockIdx.x * TM;
    const int n0c = blockIdx.y * TN;

    const int mw  = w >> 1;          // 0..3 -> m patch
    const int nw  = w & 1;           // 0..1 -> n patch
    const int m0  = mw * 16;
    const int n0w = nw * 16;

    const uint32_t sT = smem_u32(tiles);

    // ---- stage per-column params (consumed after first __syncthreads) ----
    if (tid < 128) pAn[tid] = a_norm[(size_t)(n0c + (tid >> 2)) * 4 + (tid & 3)];
    for (int id = tid; id < 640; id += 256)
        pWg[id] = w_gp[(size_t)(n0c + id / 20) * 20 + id % 20];
    if (tid < 32) pBl[tid] = b_left[n0c + tid];

    // ---- cp.async thread assignments ----
    const int arow = (tid >> 2) & 63;
    const int achk = tid & 3;
    const int brow = (tid >> 2) & 31;
    const int hs   = (tid >> 7) & 1;          // side for B loads
    const __half* aG = xt + (size_t)(b0 + arow) * FDIM + achk * 8;
    const __half* wG = (hs ? wrt : wlt) + (size_t)(n0c + brow) * FDIM + achk * 8;

#define ISSUE(cc) do { \
    const int s_ = (cc) & 1; \
    const int kt_ = (cc) * KT; \
    const uint32_t ab_ = sT + s_ * STG_B; \
    _Pragma("unroll") \
    for (int it = 0; it < 8; it++) \
        cp16(ab_ + ((it * 64 + arow) * SPADH + achk * 8) * 2, \
             aG + (size_t)it * BF + kt_); \
    _Pragma("unroll") \
    for (int it2 = 0; it2 < 4; it2++) \
        cp16(ab_ + AOFF_H * 2 + (((it2 * 2 + hs) * 32 + brow) * SPADH + achk * 8) * 2, \
             wG + (size_t)it2 * FDIM * FDIM + kt_); \
} while (0)

    // ---- accumulators: [blade][side][ntile][reg] ----
    float acc[8][2][2][4];
#pragma unroll
    for (int i = 0; i < 8; i++)
#pragma unroll
        for (int sd = 0; sd < 2; sd++)
#pragma unroll
            for (int ni = 0; ni < 2; ni++)
#pragma unroll
                for (int q = 0; q < 4; q++) acc[i][sd][ni][q] = 0.f;

    // ldmatrix lane address components (A frag, m16k16 as 4 8x8 matrices)
    const int lmrow = lane & 15;
    const int lmk   = ((lane >> 4) & 1) * 8;
    const int aoff_h = (m0 + lmrow) * SPADH + lmk;

    ISSUE(0);
    CP_COMMIT();

    for (int c = 0; c < FDIM / KT; c++) {
        if (c < FDIM / KT - 1) {
            ISSUE(c + 1);
            CP_COMMIT();
            CP_WAIT(1);
        } else {
            CP_WAIT(0);
        }
        __syncthreads();

        const int s = c & 1;
        const uint32_t tb = sT + s * STG_B;
        const __half* bsm = tiles + s * STG_H + AOFF_H +
                            (n0w + gq) * SPADH + 2 * tq;

#pragma unroll
        for (int ks = 0; ks < 2; ks++) {
            const int kk = ks * 16;
            uint32_t af[8][4];
#pragma unroll
            for (int i = 0; i < 8; i++)
                LDSM4(af[i], tb + (i * 64 * SPADH + aoff_h + kk) * 2);

#pragma unroll
            for (int g = 0; g < 4; g++) {
                uint32_t bf[2][4];
#pragma unroll
                for (int sd = 0; sd < 2; sd++) {
                    const __half* bp = bsm + ((g * 2 + sd) * 32) * SPADH + kk;
                    bf[sd][0] = *(const uint32_t*)(bp);
                    bf[sd][1] = *(const uint32_t*)(bp + 8);
                    bf[sd][2] = *(const uint32_t*)(bp + 8 * SPADH);
                    bf[sd][3] = *(const uint32_t*)(bp + 8 * SPADH + 8);
                }
                const int nb  = (g == 0 || g == 3) ? 1 : 3;
                const int ib0 = (g == 0) ? 0 : (g == 1) ? 1 : (g == 2) ? 4 : 7;
#pragma unroll
                for (int u = 0; u < 3; u++) {
                    if (u < nb) {
                        const int i = ib0 + u;
                        MMA_FP16(acc[i][0][0], af[i], bf[0][0], bf[0][1]);
                        MMA_FP16(acc[i][0][1], af[i], bf[0][2], bf[0][3]);
                        MMA_FP16(acc[i][1][0], af[i], bf[1][0], bf[1][1]);
                        MMA_FP16(acc[i][1][1], af[i], bf[1][2], bf[1][3]);
                    }
                }
            }
        }
        __syncthreads();
    }
#undef ISSUE

    // ------------------------------------------------------------------
    // Fused epilogue: per thread, 8 (b,n) points fully in registers.
    // D frag mapping: q = rr*2+cc -> (row gq+rr*8, col 2tq+cc) of n8 tile ni.
    // ------------------------------------------------------------------
    const int MASKv[8] = {0, 1, 2, 4, 3, 5, 6, 7};
    const int IDXv[8]  = {0, 1, 2, 4, 3, 5, 6, 7};
    const int GRDv[8]  = {0, 1, 1, 1, 2, 2, 2, 3};
    const signed char PIDXv[4][4][4] = {
        { { 0,-1,-1,-1}, {-1, 1,-1,-1}, {-1,-1, 2,-1}, {-1,-1,-1, 3} },
        { {-1, 4,-1,-1}, { 5,-1, 6,-1}, {-1, 7,-1, 8}, {-1,-1, 9,-1} },
        { {-1,-1,10,-1}, {-1,11,-1,12}, {13,-1,14,-1}, {-1,15,-1,-1} },
        { {-1,-1,-1,16}, {-1,-1,17,-1}, {-1,18,-1,-1}, {19,-1,-1,-1} },
    };
    const float rs2 = 0.70710678118654752440f;

#pragma unroll
    for (int ni = 0; ni < 2; ni++) {
#pragma unroll
        for (int cc = 0; cc < 2; cc++) {
            const int lcol = n0w + ni * 8 + 2 * tq + cc;
            const int gcol = n0c + lcol;
            float an[4], wp[20];
#pragma unroll
            for (int q = 0; q < 4; q++) an[q] = pAn[lcol * 4 + q];
#pragma unroll
            for (int p = 0; p < 20; p++) wp[p] = pWg[lcol * 20 + p];
            const float bias = pBl[lcol];

#pragma unroll
            for (int rr = 0; rr < 2; rr++) {
                const int grow = b0 + m0 + gq + rr * 8;
                const size_t tt = (size_t)grow * FDIM + gcol;
                const int q = rr * 2 + cc;

                float lf[8], xr[8], xv[8];
#pragma unroll
                for (int i = 0; i < 8; i++) {
                    lf[i] = acc[i][0][ni][q];
                    xr[i] = acc[i][1][ni][q];
                }
                {
                    float4 v0 = __ldg((const float4*)&x[tt * 8]);
                    float4 v1 = __ldg((const float4*)&x[tt * 8 + 4]);
                    xv[0] = v0.x; xv[1] = v0.y; xv[2] = v0.z; xv[3] = v0.w;
                    xv[4] = v1.x; xv[5] = v1.y; xv[6] = v1.z; xv[7] = v1.w;
                }

                float qs[4];
                qs[0] = xr[0] * xr[0];
                qs[1] = xr[1] * xr[1] + xr[2] * xr[2] + xr[3] * xr[3];
                qs[2] = xr[4] * xr[4] + xr[5] * xr[5] + xr[6] * xr[6];
                qs[3] = xr[7] * xr[7];

                float invn[4];
#pragma unroll
                for (int gg = 0; gg < 4; gg++) {
                    float nrm = sqrtf(sqrtf(qs[gg] * qs[gg] + 1e-16f));
                    float sig = 1.0f / (1.0f + expf(-an[gg]));
                    invn[gg] = 1.0f / (sig * (nrm - 1.0f) + 1.0f + 1e-6f);
                }

                float xrn[8];
                xrn[0] = xr[0] * invn[0];
                xrn[1] = xr[1] * invn[1];
                xrn[2] = xr[2] * invn[1];
                xrn[3] = xr[3] * invn[1];
                xrn[4] = xr[4] * invn[2];
                xrn[5] = xr[5] * invn[2];
                xrn[6] = xr[6] * invn[2];
                xrn[7] = xr[7] * invn[3];

                float gp[8];
#pragma unroll
                for (int j = 0; j < 8; j++) gp[j] = 0.f;
#pragma unroll
                for (int i = 0; i < 8; i++) {
#pragma unroll
                    for (int k = 0; k < 8; k++) {
                        const int mi = MASKv[i];
                        const int mk = MASKv[k];
                        const int j = IDXv[mi ^ mk];
                        const int s1 = ((mi >> 1) & mk);
                        const int s2 = ((mi >> 2) & mk);
                        const int sgn = ((s1 & 1) + ((s1 >> 1) & 1) + ((s1 >> 2) & 1)
                                       + (s2 & 1) + ((s2 >> 1) & 1) + ((s2 >> 2) & 1)) & 1;
                        const int p = PIDXv[GRDv[i]][GRDv[j]][GRDv[k]];
                        float term = xv[i] * xrn[k];
                        float ww = wp[p];
                        gp[j] += sgn ? (-ww * term) : (ww * term);
                    }
                }

                lf[0] += bias;

                float4 o0 = make_float4((lf[0] + gp[0]) * rs2, (lf[1] + gp[1]) * rs2,
                                        (lf[2] + gp[2]) * rs2, (lf[3] + gp[3]) * rs2);
                float4 o1 = make_float4((lf[4] + gp[4]) * rs2, (lf[5] + gp[5]) * rs2,
                                        (lf[6] + gp[6]) * rs2, (lf[7] + gp[7]) * rs2);
                *(float4*)&out[tt * 8] = o0;
                *(float4*)&out[tt * 8 + 4] = o1;
            }
        }
    }
}

// ----------------------------------------------------------------------------
// Launch — inputs (metadata order): x, w_left, b_left, w_right, a_norm, w_gp
// ----------------------------------------------------------------------------
extern "C" void kernel_launch(void* const* d_in, const int* in_sizes, int n_in,
                              void* d_out, int out_size)
{
    const float* x       = (const float*)d_in[0];
    const float* w_left  = (const float*)d_in[1];
    const float* b_left  = (const float*)d_in[2];
    const float* w_right = (const float*)d_in[3];
    const float* a_norm  = (const float*)d_in[4];
    const float* w_gp    = (const float*)d_in[5];
    float* out = (float*)d_out;

    __half *xt, *wlt, *wrt;
    cudaGetSymbolAddress((void**)&xt,  g_xt);
    cudaGetSymbolAddress((void**)&wlt, g_wl);
    cudaGetSymbolAddress((void**)&wrt, g_wr);

    cudaFuncSetAttribute(k_fused, cudaFuncAttributeMaxDynamicSharedMemorySize,
                         SMEM_TOTAL);

    k_transpose_x<<<BF / 256, 256>>>(x, xt);
    k_prep_w<<<(FDIM * FDIM) / 256, 256>>>(w_left, w_right, wlt, wrt);

    dim3 gg(BATCH / TM, FDIM / TN);
    k_fused<<<gg, 256, SMEM_TOTAL>>>(xt, wlt, wrt, x, b_left, a_norm, w_gp, out);
}

// round 13
// speedup vs baseline: 1.7318x; 1.7318x over previous
#include <cuda_runtime.h>
#include <cuda_fp16.h>
#include <cstdint>
#include <math.h>

// ----------------------------------------------------------------------------
// Problem constants
// ----------------------------------------------------------------------------
#define BATCH 8192
#define FDIM  256
#define NBL   8
#define BF    (BATCH * FDIM)   // 2,097,152

// GEMM tiling (mma.sync m16n8k16 fp16) — identical to the 145.8us R8 kernel
#define TM 128
#define TN 64
#define KT 32
#define SPADH 40               // padded smem row stride (halves) -> conflict-free

// ----------------------------------------------------------------------------
// Scratch (device globals; no allocation allowed)
// ----------------------------------------------------------------------------
__device__ __half g_xt[(size_t)NBL * BF];   // planes [i][b][k], fp16
__device__ __half g_lp[(size_t)NBL * BF];   // left planes  [i][b][n], fp16
__device__ __half g_rp[(size_t)NBL * BF];   // right planes [i][b][n], fp16
__device__ __half g_wl[4 * FDIM * FDIM];    // [g][n][k] fp16
__device__ __half g_wr[4 * FDIM * FDIM];    // [g][n][k] fp16

// ----------------------------------------------------------------------------
// helpers (base-ISA only: mma.sync + cp.async; no tcgen05 on this target)
// ----------------------------------------------------------------------------
__device__ __forceinline__ uint32_t smem_u32(const void* p) {
    uint32_t a;
    asm("{ .reg .u64 t; cvta.to.shared.u64 t, %1; cvt.u32.u64 %0, t; }"
        : "=r"(a) : "l"(p));
    return a;
}

__device__ __forceinline__ void cp16(uint32_t s, const void* g) {
    asm volatile("cp.async.cg.shared.global [%0], [%1], 16;" :: "r"(s), "l"(g));
}

#define CP_COMMIT() asm volatile("cp.async.commit_group;" ::: "memory")
#define CP_WAIT(n)  asm volatile("cp.async.wait_group %0;" :: "n"(n) : "memory")

#define MMA_FP16(d, a, b0r, b1r) \
    asm volatile( \
        "mma.sync.aligned.m16n8k16.row.col.f32.f16.f16.f32 " \
        "{%0,%1,%2,%3}, {%4,%5,%6,%7}, {%8,%9}, {%0,%1,%2,%3};" \
        : "+f"((d)[0]), "+f"((d)[1]), "+f"((d)[2]), "+f"((d)[3]) \
        : "r"((a)[0]), "r"((a)[1]), "r"((a)[2]), "r"((a)[3]), \
          "r"(b0r), "r"(b1r))

// ----------------------------------------------------------------------------
// Kernel 1: transpose x [B,F,8] -> fp16 planes [i][b][k]
// ----------------------------------------------------------------------------
__global__ void __launch_bounds__(256) k_transpose_x(
    const float* __restrict__ x, __half* __restrict__ xt)
{
    int t = blockIdx.x * 256 + threadIdx.x;   // t = b*FDIM + k
    size_t src = (size_t)t * NBL;
    float4 v0 = *(const float4*)&x[src];
    float4 v1 = *(const float4*)&x[src + 4];
    xt[0 * (size_t)BF + t] = __float2half_rn(v0.x);
    xt[1 * (size_t)BF + t] = __float2half_rn(v0.y);
    xt[2 * (size_t)BF + t] = __float2half_rn(v0.z);
    xt[3 * (size_t)BF + t] = __float2half_rn(v0.w);
    xt[4 * (size_t)BF + t] = __float2half_rn(v1.x);
    xt[5 * (size_t)BF + t] = __float2half_rn(v1.y);
    xt[6 * (size_t)BF + t] = __float2half_rn(v1.z);
    xt[7 * (size_t)BF + t] = __float2half_rn(v1.w);
}

// ----------------------------------------------------------------------------
// Kernel 2: de-interleave weights [n, k, 4] -> fp16 [g][n][k]
// ----------------------------------------------------------------------------
__global__ void __launch_bounds__(256) k_prep_w(
    const float* __restrict__ wl, const float* __restrict__ wr,
    __half* __restrict__ wlt, __half* __restrict__ wrt)
{
    int t = blockIdx.x * 256 + threadIdx.x;   // t = n*FDIM + k
    size_t src = (size_t)t * 4;
    float4 a = *(const float4*)&wl[src];
    float4 b = *(const float4*)&wr[src];
    wlt[0 * FDIM * FDIM + t] = __float2half_rn(a.x);
    wlt[1 * FDIM * FDIM + t] = __float2half_rn(a.y);
    wlt[2 * FDIM * FDIM + t] = __float2half_rn(a.z);
    wlt[3 * FDIM * FDIM + t] = __float2half_rn(a.w);
    wrt[0 * FDIM * FDIM + t] = __float2half_rn(b.x);
    wrt[1 * FDIM * FDIM + t] = __float2half_rn(b.y);
    wrt[2 * FDIM * FDIM + t] = __float2half_rn(b.z);
    wrt[3 * FDIM * FDIM + t] = __float2half_rn(b.w);
}

// ----------------------------------------------------------------------------
// Kernel 3: fp16 mma.sync dual GEMM with 2-stage cp.async pipeline.
// Identical mainloop to the verified 145.8us version; epilogue now emits fp16.
// ----------------------------------------------------------------------------
__global__ void __launch_bounds__(256, 2) k_gemm_mma(
    const __half* __restrict__ xt,
    const __half* __restrict__ wlt, const __half* __restrict__ wrt,
    __half* __restrict__ lp, __half* __restrict__ rp)
{
    __shared__ __half As [2][TM * SPADH];
    __shared__ __half BLs[2][TN * SPADH];
    __shared__ __half BRs[2][TN * SPADH];

    const int tid  = threadIdx.x;
    const int lane = tid & 31;
    const int w    = tid >> 5;
    const int gq   = lane >> 2;
    const int tq   = lane & 3;

    const int blade = blockIdx.z;
    const int grd = (blade == 0) ? 0 : (blade < 4) ? 1 : (blade < 7) ? 2 : 3;
    const int b0  = blockIdx.x * TM;
    const int n0c = blockIdx.y * TN;

    const __half* Ap  = xt  + (size_t)blade * BF + (size_t)b0 * FDIM;
    const __half* WLp = wlt + (size_t)grd * FDIM * FDIM + (size_t)n0c * FDIM;
    const __half* WRp = wrt + (size_t)grd * FDIM * FDIM + (size_t)n0c * FDIM;

    const uint32_t sA  = smem_u32(&As[0][0]);
    const uint32_t sBL = smem_u32(&BLs[0][0]);
    const uint32_t sBR = smem_u32(&BRs[0][0]);
    const uint32_t stageA  = TM * SPADH * 2;
    const uint32_t stageB  = TN * SPADH * 2;

    const int mw = w >> 1;
    const int nw = w & 1;
    const int m0 = mw * 32;
    const int n0w = nw * 32;

    const int am0 = tid >> 2;
    const int aq  = tid & 3;
    const int bn  = tid >> 2;

    float acc[2][2][4][4];
#pragma unroll
    for (int o = 0; o < 2; o++)
#pragma unroll
        for (int mi = 0; mi < 2; mi++)
#pragma unroll
            for (int ni = 0; ni < 4; ni++)
#pragma unroll
                for (int q = 0; q < 4; q++) acc[o][mi][ni][q] = 0.f;

#define ISSUE(cc) do { \
    int s_ = (cc) & 1; \
    int kt_ = (cc) * KT; \
    cp16(sA + s_ * stageA + (am0 * SPADH + aq * 8) * 2, \
         Ap + (size_t)am0 * FDIM + kt_ + aq * 8); \
    cp16(sA + s_ * stageA + ((am0 + 64) * SPADH + aq * 8) * 2, \
         Ap + (size_t)(am0 + 64) * FDIM + kt_ + aq * 8); \
    cp16(sBL + s_ * stageB + (bn * SPADH + aq * 8) * 2, \
         WLp + (size_t)bn * FDIM + kt_ + aq * 8); \
    cp16(sBR + s_ * stageB + (bn * SPADH + aq * 8) * 2, \
         WRp + (size_t)bn * FDIM + kt_ + aq * 8); \
} while (0)

    ISSUE(0);
    CP_COMMIT();

    for (int c = 0; c < FDIM / KT; c++) {
        if (c < FDIM / KT - 1) {
            ISSUE(c + 1);
            CP_COMMIT();
            CP_WAIT(1);
        } else {
            CP_WAIT(0);
        }
        __syncthreads();

        const int s = c & 1;
#pragma unroll
        for (int ks = 0; ks < 2; ks++) {
            const int kk = ks * 16 + 2 * tq;
            uint32_t a[2][4];
#pragma unroll
            for (int mi = 0; mi < 2; mi++) {
                const __half* ab = &As[s][(m0 + mi * 16 + gq) * SPADH + kk];
                a[mi][0] = *(const uint32_t*)(ab);
                a[mi][1] = *(const uint32_t*)(ab + 8 * SPADH);
                a[mi][2] = *(const uint32_t*)(ab + 8);
                a[mi][3] = *(const uint32_t*)(ab + 8 * SPADH + 8);
            }
#pragma unroll
            for (int ni = 0; ni < 4; ni++) {
                const __half* blp = &BLs[s][(n0w + ni * 8 + gq) * SPADH + kk];
                uint32_t bl0 = *(const uint32_t*)(blp);
                uint32_t bl1 = *(const uint32_t*)(blp + 8);
                const __half* brp = &BRs[s][(n0w + ni * 8 + gq) * SPADH + kk];
                uint32_t br0 = *(const uint32_t*)(brp);
                uint32_t br1 = *(const uint32_t*)(brp + 8);
#pragma unroll
                for (int mi = 0; mi < 2; mi++) {
                    MMA_FP16(acc[0][mi][ni], a[mi], bl0, bl1);
                    MMA_FP16(acc[1][mi][ni], a[mi], br0, br1);
                }
            }
        }
        __syncthreads();
    }
#undef ISSUE

    // epilogue: write fp16 half2 pairs (cols 2tq, 2tq+1 are contiguous)
#pragma unroll
    for (int o = 0; o < 2; o++) {
        __half* base = (o ? rp : lp) + (size_t)blade * BF;
#pragma unroll
        for (int mi = 0; mi < 2; mi++) {
            int row = b0 + m0 + mi * 16 + gq;
#pragma unroll
            for (int ni = 0; ni < 4; ni++) {
                int col = n0c + n0w + ni * 8 + tq * 2;
                *(__half2*)&base[(size_t)row * FDIM + col] =
                    __floats2half2_rn(acc[o][mi][ni][0], acc[o][mi][ni][1]);
                *(__half2*)&base[(size_t)(row + 8) * FDIM + col] =
                    __floats2half2_rn(acc[o][mi][ni][2], acc[o][mi][ni][3]);
            }
        }
    }
}

// ----------------------------------------------------------------------------
// Kernel 4: pointwise — now reads fp16 lp/rp (half the intermediate traffic)
// ----------------------------------------------------------------------------
__global__ void __launch_bounds__(256) k_pointwise(
    const float* __restrict__ x,
    const __half* __restrict__ lp, const __half* __restrict__ rp,
    const float* __restrict__ b_left, const float* __restrict__ a_norm,
    const float* __restrict__ w_gp, float* __restrict__ out)
{
    const int MASKv[8] = {0, 1, 2, 4, 3, 5, 6, 7};
    const int IDXv[8]  = {0, 1, 2, 4, 3, 5, 6, 7};
    const int GRDv[8]  = {0, 1, 1, 1, 2, 2, 2, 3};
    const signed char PIDXv[4][4][4] = {
        { { 0,-1,-1,-1}, {-1, 1,-1,-1}, {-1,-1, 2,-1}, {-1,-1,-1, 3} },
        { {-1, 4,-1,-1}, { 5,-1, 6,-1}, {-1, 7,-1, 8}, {-1,-1, 9,-1} },
        { {-1,-1,10,-1}, {-1,11,-1,12}, {13,-1,14,-1}, {-1,15,-1,-1} },
        { {-1,-1,-1,16}, {-1,-1,17,-1}, {-1,18,-1,-1}, {19,-1,-1,-1} },
    };

    int t = blockIdx.x * 256 + threadIdx.x;   // t = b*FDIM + n
    int n = t & (FDIM - 1);

    float xr[8], lf[8], xv[8];
#pragma unroll
    for (int i = 0; i < 8; i++) {
        xr[i] = __half2float(rp[(size_t)i * BF + t]);
        lf[i] = __half2float(lp[(size_t)i * BF + t]);
    }
    {
        float4 v0 = *(const float4*)&x[(size_t)t * 8];
        float4 v1 = *(const float4*)&x[(size_t)t * 8 + 4];
        xv[0] = v0.x; xv[1] = v0.y; xv[2] = v0.z; xv[3] = v0.w;
        xv[4] = v1.x; xv[5] = v1.y; xv[6] = v1.z; xv[7] = v1.w;
    }

    float qs[4];
    qs[0] = xr[0] * xr[0];
    qs[1] = xr[1] * xr[1] + xr[2] * xr[2] + xr[3] * xr[3];
    qs[2] = xr[4] * xr[4] + xr[5] * xr[5] + xr[6] * xr[6];
    qs[3] = xr[7] * xr[7];

    float invn[4];
#pragma unroll
    for (int gg = 0; gg < 4; gg++) {
        float nrm = sqrtf(sqrtf(qs[gg] * qs[gg] + 1e-16f));
        float a = a_norm[n * 4 + gg];
        float sig = 1.0f / (1.0f + expf(-a));
        float d = sig * (nrm - 1.0f) + 1.0f + 1e-6f;
        invn[gg] = 1.0f / d;
    }

    float xrn[8];
    xrn[0] = xr[0] * invn[0];
    xrn[1] = xr[1] * invn[1];
    xrn[2] = xr[2] * invn[1];
    xrn[3] = xr[3] * invn[1];
    xrn[4] = xr[4] * invn[2];
    xrn[5] = xr[5] * invn[2];
    xrn[6] = xr[6] * invn[2];
    xrn[7] = xr[7] * invn[3];

    float wp[20];
#pragma unroll
    for (int p = 0; p < 20; p++) wp[p] = __ldg(&w_gp[n * 20 + p]);

    float gp[8];
#pragma unroll
    for (int j = 0; j < 8; j++) gp[j] = 0.f;

#pragma unroll
    for (int i = 0; i < 8; i++) {
#pragma unroll
        for (int k = 0; k < 8; k++) {
            const int mi = MASKv[i];
            const int mk = MASKv[k];
            const int j = IDXv[mi ^ mk];
            const int s1 = ((mi >> 1) & mk);
            const int s2 = ((mi >> 2) & mk);
            const int sgn = ((s1 & 1) + ((s1 >> 1) & 1) + ((s1 >> 2) & 1)
                           + (s2 & 1) + ((s2 >> 1) & 1) + ((s2 >> 2) & 1)) & 1;
            const int p = PIDXv[GRDv[i]][GRDv[j]][GRDv[k]];
            float term = xv[i] * xrn[k];
            float ww = wp[p];
            gp[j] += sgn ? (-ww * term) : (ww * term);
        }
    }

    lf[0] += b_left[n];

    const float rs2 = 0.70710678118654752440f;
    float4 o0 = make_float4((lf[0] + gp[0]) * rs2, (lf[1] + gp[1]) * rs2,
                            (lf[2] + gp[2]) * rs2, (lf[3] + gp[3]) * rs2);
    float4 o1 = make_float4((lf[4] + gp[4]) * rs2, (lf[5] + gp[5]) * rs2,
                            (lf[6] + gp[6]) * rs2, (lf[7] + gp[7]) * rs2);
    *(float4*)&out[(size_t)t * 8] = o0;
    *(float4*)&out[(size_t)t * 8 + 4] = o1;
}

// ----------------------------------------------------------------------------
// Launch — inputs (metadata order): x, w_left, b_left, w_right, a_norm, w_gp
// ----------------------------------------------------------------------------
extern "C" void kernel_launch(void* const* d_in, const int* in_sizes, int n_in,
                              void* d_out, int out_size)
{
    const float* x       = (const float*)d_in[0];
    const float* w_left  = (const float*)d_in[1];
    const float* b_left  = (const float*)d_in[2];
    const float* w_right = (const float*)d_in[3];
    const float* a_norm  = (const float*)d_in[4];
    const float* w_gp    = (const float*)d_in[5];
    float* out = (float*)d_out;

    __half *xt, *wlt, *wrt, *lp, *rp;
    cudaGetSymbolAddress((void**)&xt,  g_xt);
    cudaGetSymbolAddress((void**)&lp,  g_lp);
    cudaGetSymbolAddress((void**)&rp,  g_rp);
    cudaGetSymbolAddress((void**)&wlt, g_wl);
    cudaGetSymbolAddress((void**)&wrt, g_wr);

    k_transpose_x<<<BF / 256, 256>>>(x, xt);
    k_prep_w<<<(FDIM * FDIM) / 256, 256>>>(w_left, w_right, wlt, wrt);

    dim3 gg(BATCH / TM, FDIM / TN, NBL);
    k_gemm_mma<<<gg, 256>>>(xt, wlt, wrt, lp, rp);

    k_pointwise<<<BF / 256, 256>>>(x, lp, rp, b_left, a_norm, w_gp, out);
}